// round 7
// baseline (speedup 1.0000x reference)
#include <cuda_runtime.h>
#include <math.h>
#include <stdint.h>

// Problem constants
#define BATCH 512
#define HDIM  64
#define OBS   8
#define PRE   12
#define G3    192   // 3*H

// Scratch (device globals — no allocation allowed)
__device__ float  g_h[BATCH * HDIM];                 // GRU hidden state
// u double-buffered: [buf][(j>>3)*256 + (kt*4+tig)*8 + (j&7)] = {u[j][kt*8+tig], u[j][kt*8+tig+4]}
__device__ float2 g_u2[2][(BATCH / 8) * 32 * 8];
// hpart double-buffered: [buf][(j>>3)*256 + cp*8 + (j&7)] = {hp[j][2cp], hp[j][2cp+1]}
__device__ float2 g_hp2[2][(BATCH / 8) * 32 * 8];
__device__ float  g_WihT[HDIM * G3];                 // W_ih transposed [d][g]
__device__ float  g_WhhT[HDIM * G3];                 // W_hh transposed [d][g]
// B fragments: [(ct*4+ktp)*32 + lane] = {B(2ktp).x, B(2ktp).y, B(2ktp+1).x, B(2ktp+1).y}
__device__ uint4  g_B4[32 * 32];

__device__ __forceinline__ uint32_t f2tf32(float x) {
    uint32_t u;
    asm("cvt.rna.tf32.f32 %0, %1;" : "=r"(u) : "f"(x));
    return u;
}

__device__ __forceinline__ void mma_tf32(float& d0, float& d1, float& d2, float& d3,
                                         uint32_t a0, uint32_t a1, uint32_t a2, uint32_t a3,
                                         uint32_t b0, uint32_t b1) {
    asm volatile("mma.sync.aligned.m16n8k8.row.col.f32.tf32.tf32.f32 "
                 "{%0,%1,%2,%3}, {%4,%5,%6,%7}, {%8,%9}, {%0,%1,%2,%3};"
                 : "+f"(d0), "+f"(d1), "+f"(d2), "+f"(d3)
                 : "r"(a0), "r"(a1), "r"(a2), "r"(a3), "r"(b0), "r"(b1));
}

__device__ __forceinline__ float fsigmoid(float x) {
    return 1.0f / (1.0f + __expf(-x));
}
__device__ __forceinline__ float ftanh(float x) {
    return 2.0f / (1.0f + __expf(-2.0f * x)) - 1.0f;
}

// scalar index into the float2 u/hp layouts, viewed as float
__device__ __forceinline__ int u_scalar_idx(int j, int k) {
    int kt = k >> 3, tig = k & 3, s = (k >> 2) & 1;
    return (j >> 3) * 512 + (kt * 4 + tig) * 16 + (j & 7) * 2 + s;
}
__device__ __forceinline__ int hp_scalar_idx(int j, int c) {
    return (j >> 3) * 512 + (c >> 1) * 16 + (j & 7) * 2 + (c & 1);
}

// ---------------------------------------------------------------------------
// Init: copy group_track into out, build u2/hp2 (buf 0), zero GRU h,
// transpose W_ih / W_hh, precompute B fragments.
// Grid: BATCH + G3 + 32 blocks x 64 threads.
// ---------------------------------------------------------------------------
__global__ void init_kernel(const float* __restrict__ hidden,
                            const float* __restrict__ gt,
                            const float* __restrict__ W_ih,
                            const float* __restrict__ W_hh,
                            const float* __restrict__ W_rel,
                            const float* __restrict__ W_pool,
                            const float* __restrict__ b_pool,
                            float* __restrict__ out)
{
    int bid = blockIdx.x;
    int c = threadIdx.x;
    if (bid < BATCH) {
        int i = bid;
        // copy observed track: out[i, 0:8, :]
        if (c < 2 * OBS) out[i * 2 * (OBS + PRE) + c] = gt[i * 2 * OBS + c];
        // u (buf 0) from last observed position
        float px = gt[i * 2 * OBS + 2 * (OBS - 1) + 0];
        float py = gt[i * 2 * OBS + 2 * (OBS - 1) + 1];
        ((float*)g_u2[0])[u_scalar_idx(i, c)] = px * W_rel[c] + py * W_rel[HDIM + c];
        // hp (buf 0) from hidden_state
        float acc = b_pool[c];
        #pragma unroll 8
        for (int d = 0; d < HDIM; ++d)
            acc += hidden[i * HDIM + d] * W_pool[(HDIM + d) * HDIM + c];
        ((float*)g_hp2[0])[hp_scalar_idx(i, c)] = acc;
        g_h[i * HDIM + c] = 0.0f;
    } else if (bid < BATCH + G3) {
        int g = bid - BATCH;   // 0..191
        int d = c;             // 0..63
        g_WihT[d * G3 + g] = W_ih[g * HDIM + d];
        g_WhhT[d * G3 + g] = W_hh[g * HDIM + d];
    } else if (c < 32) {
        // B fragment precompute for one (ct, ktp): covers kt = 2ktp, 2ktp+1
        int q = bid - (BATCH + G3);   // 0..31
        int ktp = q & 3, ct = q >> 2;
        int tig = c & 3, gid = c >> 2;
        int cc = ct * 8 + gid;
        int ka = (2 * ktp) * 8 + tig;
        int kb = (2 * ktp + 1) * 8 + tig;
        uint32_t b0 = f2tf32(W_pool[ka * HDIM + cc]);
        uint32_t b1 = f2tf32(W_pool[(ka + 4) * HDIM + cc]);
        uint32_t b2 = f2tf32(W_pool[kb * HDIM + cc]);
        uint32_t b3 = f2tf32(W_pool[(kb + 4) * HDIM + cc]);
        g_B4[q * 32 + c] = make_uint4(b0, b1, b2, b3);
    }
}

// ---------------------------------------------------------------------------
// Fused step: block = one agent i. Spool over all 512 j (4 warps x 8 stages
// of 16 j, loads front-batched per stage, hp folded in post-MMA), then
// pos -> out, emb, GRU, and next-step u/hp (double-buffered).
// Grid: 512 blocks x 128 threads.
// ---------------------------------------------------------------------------
__global__ void __launch_bounds__(128, 4) step_kernel(
    const float* __restrict__ b_rel,
    const float* __restrict__ W_emb, const float* __restrict__ b_emb,
    const float* __restrict__ b_ih,  const float* __restrict__ b_hh,
    const float* __restrict__ W_pos, const float* __restrict__ b_pos,
    const float* __restrict__ W_rel, const float* __restrict__ W_pool,
    const float* __restrict__ b_pool, float* __restrict__ out, int step)
{
    __shared__ float ar_s[HDIM];      // b_rel[k] - u_i[k]
    __shared__ float red_s[4][HDIM];  // cross-warp max reduction
    __shared__ float pooled_s[HDIM];
    __shared__ float pos_s[2];
    __shared__ float emb_s[HDIM];
    __shared__ float hv_s[HDIM];
    __shared__ float hn_s[HDIM];

    int buf  = step & 1;
    int nbuf = buf ^ 1;
    const float2* __restrict__ u2r  = g_u2[buf];
    const float2* __restrict__ hp2r = g_hp2[buf];

    int i = blockIdx.x;
    int t = threadIdx.x;
    int w = t >> 5, l = t & 31;
    int gid = l >> 2, tig = l & 3;

    if (t < HDIM)
        ar_s[t] = b_rel[t] - ((const float*)u2r)[u_scalar_idx(i, t)];
    __syncthreads();

    // per-lane (k, k+4) bias pairs
    float2 ar2[8];
    #pragma unroll
    for (int kt = 0; kt < 8; ++kt) {
        int k0 = kt * 8 + tig;
        ar2[kt] = make_float2(ar_s[k0], ar_s[k0 + 4]);
    }

    float mx[8][2];
    #pragma unroll
    for (int ct = 0; ct < 8; ++ct) { mx[ct][0] = 0.0f; mx[ct][1] = 0.0f; }  // relu => max>=0

    // warp w owns j in [w*128, w*128+128), 8 stages of one 16-row jtile
    for (int s = 0; s < 8; ++s) {
        int rb = (w * 16 + s * 2) * 256;     // float2 base: rows jb..jb+7
        const float2* __restrict__ u0 = u2r + rb;
        const float2* __restrict__ u1 = u2r + rb + 256;     // rows jb+8..jb+15
        const float2* __restrict__ hp0 = hp2r + rb;
        const float2* __restrict__ hp1 = hp2r + rb + 256;

        // -- batched loads: 16 u + 16 hp float2 LDGs, all independent --
        float2 uv0[8], uv1[8];
        #pragma unroll
        for (int kt = 0; kt < 8; ++kt) {
            uv0[kt] = u0[(kt * 4 + tig) * 8 + gid];
            uv1[kt] = u1[(kt * 4 + tig) * 8 + gid];
        }
        float2 hva[4], hvb[4];   // hp fragments: [ct][jhalf] packed as 2 groups of 4 ct
        float2 hva1[4], hvb1[4];
        #pragma unroll
        for (int ct = 0; ct < 4; ++ct) {
            hva[ct]  = hp0[(ct * 4 + tig) * 8 + gid];
            hva1[ct] = hp1[(ct * 4 + tig) * 8 + gid];
        }
        #pragma unroll
        for (int ct = 0; ct < 4; ++ct) {
            hvb[ct]  = hp0[((ct + 4) * 4 + tig) * 8 + gid];
            hvb1[ct] = hp1[((ct + 4) * 4 + tig) * 8 + gid];
        }

        // A fragments (consume u loads; uv regs die here)
        uint32_t afr[8][4];
        #pragma unroll
        for (int kt = 0; kt < 8; ++kt) {
            afr[kt][0] = f2tf32(fmaxf(uv0[kt].x + ar2[kt].x, 0.0f));
            afr[kt][1] = f2tf32(fmaxf(uv1[kt].x + ar2[kt].x, 0.0f));
            afr[kt][2] = f2tf32(fmaxf(uv0[kt].y + ar2[kt].y, 0.0f));
            afr[kt][3] = f2tf32(fmaxf(uv1[kt].y + ar2[kt].y, 0.0f));
        }

        // -- MMA chains: d zero-init, hp added after (no loads mid-chain) --
        #pragma unroll
        for (int ct = 0; ct < 8; ++ct) {
            float d0 = 0.0f, d1 = 0.0f, d2 = 0.0f, d3 = 0.0f;
            #pragma unroll
            for (int ktp = 0; ktp < 4; ++ktp) {
                uint4 B = g_B4[(ct * 4 + ktp) * 32 + l];
                mma_tf32(d0, d1, d2, d3,
                         afr[2 * ktp][0], afr[2 * ktp][1], afr[2 * ktp][2], afr[2 * ktp][3],
                         B.x, B.y);
                mma_tf32(d0, d1, d2, d3,
                         afr[2 * ktp + 1][0], afr[2 * ktp + 1][1], afr[2 * ktp + 1][2], afr[2 * ktp + 1][3],
                         B.z, B.w);
            }
            float2 h0 = (ct < 4) ? hva[ct & 3] : hvb[ct & 3];
            float2 h1 = (ct < 4) ? hva1[ct & 3] : hvb1[ct & 3];
            d0 += h0.x; d1 += h0.y; d2 += h1.x; d3 += h1.y;
            mx[ct][0] = fmaxf(mx[ct][0], fmaxf(d0, d2));
            mx[ct][1] = fmaxf(mx[ct][1], fmaxf(d1, d3));
        }
    }

    // Reduce across lane groups (gid), write per-warp result
    #pragma unroll
    for (int ct = 0; ct < 8; ++ct) {
        #pragma unroll
        for (int pp = 0; pp < 2; ++pp) {
            float v = fmaxf(mx[ct][pp], 0.0f);
            v = fmaxf(v, __shfl_xor_sync(0xffffffffu, v, 4));
            v = fmaxf(v, __shfl_xor_sync(0xffffffffu, v, 8));
            v = fmaxf(v, __shfl_xor_sync(0xffffffffu, v, 16));
            if (gid == 0) red_s[w][ct * 8 + 2 * tig + pp] = v;
        }
    }
    __syncthreads();
    if (t < HDIM)
        pooled_s[t] = fmaxf(fmaxf(red_s[0][t], red_s[1][t]), fmaxf(red_s[2][t], red_s[3][t]));
    __syncthreads();

    // ---- update tail ----
    if (w == 0) {
        float p0 = pooled_s[l], p1 = pooled_s[l + 32];
        float px = p0 * W_pos[l * 2 + 0] + p1 * W_pos[(l + 32) * 2 + 0];
        float py = p0 * W_pos[l * 2 + 1] + p1 * W_pos[(l + 32) * 2 + 1];
        #pragma unroll
        for (int s = 16; s; s >>= 1) {
            px += __shfl_xor_sync(0xffffffffu, px, s);
            py += __shfl_xor_sync(0xffffffffu, py, s);
        }
        if (l == 0) {
            px += b_pos[0]; py += b_pos[1];
            out[i * 2 * (OBS + PRE) + (OBS + step) * 2 + 0] = px;
            out[i * 2 * (OBS + PRE) + (OBS + step) * 2 + 1] = py;
            pos_s[0] = px; pos_s[1] = py;
        }
    }
    __syncthreads();

    float px = pos_s[0], py = pos_s[1];
    if (t < HDIM) {
        // next-step u
        ((float*)g_u2[nbuf])[u_scalar_idx(i, t)] = px * W_rel[t] + py * W_rel[HDIM + t];
        // emb; stage h
        emb_s[t] = px * W_emb[t] + py * W_emb[HDIM + t] + b_emb[t];
        hv_s[t]  = g_h[i * HDIM + t];
    }
    __syncthreads();

    if (t < HDIM) {
        int c = t;
        float gir = b_ih[c], giz = b_ih[64 + c], gin = b_ih[128 + c];
        float ghr = b_hh[c], ghz = b_hh[64 + c], ghn = b_hh[128 + c];
        #pragma unroll 8
        for (int d = 0; d < HDIM; ++d) {
            float ed = emb_s[d], hd = hv_s[d];
            gir += ed * g_WihT[d * G3 + c];
            giz += ed * g_WihT[d * G3 + 64 + c];
            gin += ed * g_WihT[d * G3 + 128 + c];
            ghr += hd * g_WhhT[d * G3 + c];
            ghz += hd * g_WhhT[d * G3 + 64 + c];
            ghn += hd * g_WhhT[d * G3 + 128 + c];
        }
        float r = fsigmoid(gir + ghr);
        float z = fsigmoid(giz + ghz);
        float n = ftanh(gin + r * ghn);
        float hn = (1.0f - z) * n + z * hv_s[c];
        g_h[i * HDIM + c] = hn;
        hn_s[c] = hn;
    }
    __syncthreads();

    if (t < HDIM) {
        int c = t;
        float hp = b_pool[c];
        #pragma unroll 8
        for (int d = 0; d < HDIM; ++d)
            hp += hn_s[d] * W_pool[(HDIM + d) * HDIM + c];
        ((float*)g_hp2[nbuf])[hp_scalar_idx(i, c)] = hp;
    }
}

// ---------------------------------------------------------------------------
extern "C" void kernel_launch(void* const* d_in, const int* in_sizes, int n_in,
                              void* d_out, int out_size)
{
    const float* hidden = (const float*)d_in[0];
    const float* gt     = (const float*)d_in[1];
    const float* W_emb  = (const float*)d_in[2];
    const float* b_emb  = (const float*)d_in[3];
    const float* W_ih   = (const float*)d_in[4];
    const float* W_hh   = (const float*)d_in[5];
    const float* b_ih   = (const float*)d_in[6];
    const float* b_hh   = (const float*)d_in[7];
    const float* W_pos  = (const float*)d_in[8];
    const float* b_pos  = (const float*)d_in[9];
    const float* W_rel  = (const float*)d_in[10];
    const float* b_rel  = (const float*)d_in[11];
    const float* W_pool = (const float*)d_in[12];
    const float* b_pool = (const float*)d_in[13];
    float* out = (float*)d_out;

    init_kernel<<<BATCH + G3 + 32, 64>>>(hidden, gt, W_ih, W_hh, W_rel, W_pool, b_pool, out);
    for (int s = 0; s < PRE; ++s) {
        step_kernel<<<BATCH, 128>>>(b_rel, W_emb, b_emb, b_ih, b_hh,
                                    W_pos, b_pos, W_rel, W_pool, b_pool,
                                    out, s);
    }
}

// round 8
// speedup vs baseline: 1.2157x; 1.2157x over previous
#include <cuda_runtime.h>
#include <math.h>
#include <stdint.h>

// Problem constants
#define BATCH 512
#define HDIM  64
#define OBS   8
#define PRE   12
#define G3    192   // 3*H
#define NBUF  (PRE + 1)

// Scratch (device globals — no allocation allowed)
__device__ float  g_h[BATCH * HDIM];                 // GRU hidden state (block-private)
// u per-step buffers: [step][(j>>3)*256 + (kt*4+tig)*8 + (j&7)] = {u[j][k], u[j][k+4]}
__device__ float2 g_u2[NBUF][(BATCH / 8) * 32 * 8];
// hpart per-step buffers: [step][(j>>3)*256 + cp*8 + (j&7)] = {hp[j][2cp], hp[j][2cp+1]}
__device__ float2 g_hp2[NBUF][(BATCH / 8) * 32 * 8];
__device__ float  g_WihT[HDIM * G3];                 // W_ih transposed [d][g]
__device__ float  g_WhhT[HDIM * G3];                 // W_hh transposed [d][g]
// B fragments: [(ct*4+ktp)*32 + lane] = {B(2ktp).x, B(2ktp).y, B(2ktp+1).x, B(2ktp+1).y}
__device__ uint4  g_B4[32 * 32];
// grid barrier state
__device__ unsigned g_bar_cnt;
__device__ unsigned g_bar_rel;

__device__ __forceinline__ uint32_t f2tf32(float x) {
    uint32_t u;
    asm("cvt.rna.tf32.f32 %0, %1;" : "=r"(u) : "f"(x));
    return u;
}

__device__ __forceinline__ void mma_tf32(float& d0, float& d1, float& d2, float& d3,
                                         uint32_t a0, uint32_t a1, uint32_t a2, uint32_t a3,
                                         uint32_t b0, uint32_t b1) {
    asm volatile("mma.sync.aligned.m16n8k8.row.col.f32.tf32.tf32.f32 "
                 "{%0,%1,%2,%3}, {%4,%5,%6,%7}, {%8,%9}, {%0,%1,%2,%3};"
                 : "+f"(d0), "+f"(d1), "+f"(d2), "+f"(d3)
                 : "r"(a0), "r"(a1), "r"(a2), "r"(a3), "r"(b0), "r"(b1));
}

__device__ __forceinline__ float fsigmoid(float x) {
    return 1.0f / (1.0f + __expf(-x));
}
__device__ __forceinline__ float ftanh(float x) {
    return 2.0f / (1.0f + __expf(-2.0f * x)) - 1.0f;
}

// scalar index into the float2 u/hp layouts, viewed as float
__device__ __forceinline__ int u_scalar_idx(int j, int k) {
    int kt = k >> 3, tig = k & 3, s = (k >> 2) & 1;
    return (j >> 3) * 512 + (kt * 4 + tig) * 16 + (j & 7) * 2 + s;
}
__device__ __forceinline__ int hp_scalar_idx(int j, int c) {
    return (j >> 3) * 512 + (c >> 1) * 16 + (j & 7) * 2 + (c & 1);
}

// ---------------------------------------------------------------------------
// Init: copy group_track into out, build u/hp (buffer 0), zero GRU h and
// barrier state, transpose W_ih / W_hh, precompute B fragments.
// Grid: BATCH + G3 + 32 blocks x 64 threads.
// ---------------------------------------------------------------------------
__global__ void init_kernel(const float* __restrict__ hidden,
                            const float* __restrict__ gt,
                            const float* __restrict__ W_ih,
                            const float* __restrict__ W_hh,
                            const float* __restrict__ W_rel,
                            const float* __restrict__ W_pool,
                            const float* __restrict__ b_pool,
                            float* __restrict__ out)
{
    int bid = blockIdx.x;
    int c = threadIdx.x;
    if (bid == 0 && c == 0) { g_bar_cnt = 0u; g_bar_rel = 0u; }
    if (bid < BATCH) {
        int i = bid;
        // copy observed track: out[i, 0:8, :]
        if (c < 2 * OBS) out[i * 2 * (OBS + PRE) + c] = gt[i * 2 * OBS + c];
        // u (buffer 0) from last observed position
        float px = gt[i * 2 * OBS + 2 * (OBS - 1) + 0];
        float py = gt[i * 2 * OBS + 2 * (OBS - 1) + 1];
        ((float*)g_u2[0])[u_scalar_idx(i, c)] = px * W_rel[c] + py * W_rel[HDIM + c];
        // hp (buffer 0) from hidden_state
        float acc = b_pool[c];
        #pragma unroll 8
        for (int d = 0; d < HDIM; ++d)
            acc += hidden[i * HDIM + d] * W_pool[(HDIM + d) * HDIM + c];
        ((float*)g_hp2[0])[hp_scalar_idx(i, c)] = acc;
        g_h[i * HDIM + c] = 0.0f;
    } else if (bid < BATCH + G3) {
        int g = bid - BATCH;   // 0..191
        int d = c;             // 0..63
        g_WihT[d * G3 + g] = W_ih[g * HDIM + d];
        g_WhhT[d * G3 + g] = W_hh[g * HDIM + d];
    } else if (c < 32) {
        // B fragment precompute for one (ct, ktp): covers kt = 2ktp, 2ktp+1
        int q = bid - (BATCH + G3);   // 0..31
        int ktp = q & 3, ct = q >> 2;
        int tig = c & 3, gid = c >> 2;
        int cc = ct * 8 + gid;
        int ka = (2 * ktp) * 8 + tig;
        int kb = (2 * ktp + 1) * 8 + tig;
        uint32_t b0 = f2tf32(W_pool[ka * HDIM + cc]);
        uint32_t b1 = f2tf32(W_pool[(ka + 4) * HDIM + cc]);
        uint32_t b2 = f2tf32(W_pool[kb * HDIM + cc]);
        uint32_t b3 = f2tf32(W_pool[(kb + 4) * HDIM + cc]);
        g_B4[q * 32 + c] = make_uint4(b0, b1, b2, b3);
    }
}

// ---------------------------------------------------------------------------
// Persistent fused decoder: block = one agent i, loops over all 12 steps with
// a hand-rolled grid barrier between steps. All 512 blocks are co-resident
// (128 regs x 128 thr -> 4 blocks/SM x 148 SMs = 592 slots), so the spin
// barrier cannot deadlock. Per step: spool over all 512 j (4 warps x 4 tiles
// of 32 j), then pos -> out, emb, GRU, next-step u/hp (fresh buffer per step
// => no stale-L1 hazard: each buffer is written once, then read).
// Grid: 512 blocks x 128 threads.
// ---------------------------------------------------------------------------
__global__ void __launch_bounds__(128, 4) decode_kernel(
    const float* __restrict__ b_rel,
    const float* __restrict__ W_emb, const float* __restrict__ b_emb,
    const float* __restrict__ b_ih,  const float* __restrict__ b_hh,
    const float* __restrict__ W_pos, const float* __restrict__ b_pos,
    const float* __restrict__ W_rel, const float* __restrict__ W_pool,
    const float* __restrict__ b_pool, float* __restrict__ out)
{
    __shared__ float ar_s[HDIM];      // b_rel[k] - u_i[k]
    __shared__ float red_s[4][HDIM];  // cross-warp max reduction
    __shared__ float pooled_s[HDIM];
    __shared__ float pos_s[2];
    __shared__ float emb_s[HDIM];
    __shared__ float hv_s[HDIM];
    __shared__ float hn_s[HDIM];

    int i = blockIdx.x;
    int t = threadIdx.x;
    int w = t >> 5, l = t & 31;
    int gid = l >> 2, tig = l & 3;

    #pragma unroll 1
    for (int step = 0; step < PRE; ++step) {
        const float2* __restrict__ u2r  = g_u2[step];
        const float2* __restrict__ hp2r = g_hp2[step];

        if (t < HDIM)
            ar_s[t] = b_rel[t] - ((const float*)u2r)[u_scalar_idx(i, t)];
        __syncthreads();

        // per-lane (k, k+4) bias pairs
        float2 ar2[8];
        #pragma unroll
        for (int kt = 0; kt < 8; ++kt) {
            int k0 = kt * 8 + tig;
            ar2[kt] = make_float2(ar_s[k0], ar_s[k0 + 4]);
        }

        float mx[8][2];
        #pragma unroll
        for (int ct = 0; ct < 8; ++ct) { mx[ct][0] = 0.0f; mx[ct][1] = 0.0f; }  // relu => max>=0

        for (int p = 0; p < 4; ++p) {
            int jb = p * 128 + w * 32;
            int rb = (jb >> 3) * 256;   // float2 row-block base (8 rows per 256)

            // A fragments: e = relu(u_j + ar), tf32, for 2 jtiles x 8 ktiles
            uint32_t afr[2][8][4];
            #pragma unroll
            for (int jt = 0; jt < 2; ++jt) {
                int r0 = rb + jt * 512;     // rows jb+16jt .. +7
                #pragma unroll
                for (int kt = 0; kt < 8; ++kt) {
                    float2 v0 = u2r[r0 + (kt * 4 + tig) * 8 + gid];
                    float2 v1 = u2r[r0 + 256 + (kt * 4 + tig) * 8 + gid];
                    afr[jt][kt][0] = f2tf32(fmaxf(v0.x + ar2[kt].x, 0.0f));
                    afr[jt][kt][1] = f2tf32(fmaxf(v1.x + ar2[kt].x, 0.0f));
                    afr[jt][kt][2] = f2tf32(fmaxf(v0.y + ar2[kt].y, 0.0f));
                    afr[jt][kt][3] = f2tf32(fmaxf(v1.y + ar2[kt].y, 0.0f));
                }
            }

            #pragma unroll
            for (int ct = 0; ct < 8; ++ct) {
                // C init = hpart fragments (float2 covers both c columns of a lane)
                float d[2][4];
                #pragma unroll
                for (int jt = 0; jt < 2; ++jt) {
                    int r0 = rb + jt * 512;
                    float2 c0 = hp2r[r0 + (ct * 4 + tig) * 8 + gid];
                    float2 c1 = hp2r[r0 + 256 + (ct * 4 + tig) * 8 + gid];
                    d[jt][0] = c0.x; d[jt][1] = c0.y;
                    d[jt][2] = c1.x; d[jt][3] = c1.y;
                }
                #pragma unroll
                for (int ktp = 0; ktp < 4; ++ktp) {
                    uint4 B = g_B4[(ct * 4 + ktp) * 32 + l];
                    mma_tf32(d[0][0], d[0][1], d[0][2], d[0][3],
                             afr[0][2 * ktp][0], afr[0][2 * ktp][1], afr[0][2 * ktp][2], afr[0][2 * ktp][3],
                             B.x, B.y);
                    mma_tf32(d[0][0], d[0][1], d[0][2], d[0][3],
                             afr[0][2 * ktp + 1][0], afr[0][2 * ktp + 1][1], afr[0][2 * ktp + 1][2], afr[0][2 * ktp + 1][3],
                             B.z, B.w);
                    mma_tf32(d[1][0], d[1][1], d[1][2], d[1][3],
                             afr[1][2 * ktp][0], afr[1][2 * ktp][1], afr[1][2 * ktp][2], afr[1][2 * ktp][3],
                             B.x, B.y);
                    mma_tf32(d[1][0], d[1][1], d[1][2], d[1][3],
                             afr[1][2 * ktp + 1][0], afr[1][2 * ktp + 1][1], afr[1][2 * ktp + 1][2], afr[1][2 * ktp + 1][3],
                             B.z, B.w);
                }
                mx[ct][0] = fmaxf(mx[ct][0], fmaxf(fmaxf(d[0][0], d[0][2]), fmaxf(d[1][0], d[1][2])));
                mx[ct][1] = fmaxf(mx[ct][1], fmaxf(fmaxf(d[0][1], d[0][3]), fmaxf(d[1][1], d[1][3])));
            }
        }

        // Reduce across lane groups (gid), write per-warp result
        #pragma unroll
        for (int ct = 0; ct < 8; ++ct) {
            #pragma unroll
            for (int pp = 0; pp < 2; ++pp) {
                float v = mx[ct][pp];
                v = fmaxf(v, __shfl_xor_sync(0xffffffffu, v, 4));
                v = fmaxf(v, __shfl_xor_sync(0xffffffffu, v, 8));
                v = fmaxf(v, __shfl_xor_sync(0xffffffffu, v, 16));
                if (gid == 0) red_s[w][ct * 8 + 2 * tig + pp] = v;
            }
        }
        __syncthreads();
        if (t < HDIM)
            pooled_s[t] = fmaxf(fmaxf(red_s[0][t], red_s[1][t]), fmaxf(red_s[2][t], red_s[3][t]));
        __syncthreads();

        // ---- update tail ----
        if (w == 0) {
            float p0 = pooled_s[l], p1 = pooled_s[l + 32];
            float px = p0 * W_pos[l * 2 + 0] + p1 * W_pos[(l + 32) * 2 + 0];
            float py = p0 * W_pos[l * 2 + 1] + p1 * W_pos[(l + 32) * 2 + 1];
            #pragma unroll
            for (int s = 16; s; s >>= 1) {
                px += __shfl_xor_sync(0xffffffffu, px, s);
                py += __shfl_xor_sync(0xffffffffu, py, s);
            }
            if (l == 0) {
                px += b_pos[0]; py += b_pos[1];
                out[i * 2 * (OBS + PRE) + (OBS + step) * 2 + 0] = px;
                out[i * 2 * (OBS + PRE) + (OBS + step) * 2 + 1] = py;
                pos_s[0] = px; pos_s[1] = py;
            }
        }
        __syncthreads();

        float px = pos_s[0], py = pos_s[1];
        if (t < HDIM) {
            // next-step u (fresh buffer: step+1)
            ((float*)g_u2[step + 1])[u_scalar_idx(i, t)] = px * W_rel[t] + py * W_rel[HDIM + t];
            // emb; stage h
            emb_s[t] = px * W_emb[t] + py * W_emb[HDIM + t] + b_emb[t];
            hv_s[t]  = g_h[i * HDIM + t];
        }
        __syncthreads();

        if (t < HDIM) {
            int c = t;
            float gir = b_ih[c], giz = b_ih[64 + c], gin = b_ih[128 + c];
            float ghr = b_hh[c], ghz = b_hh[64 + c], ghn = b_hh[128 + c];
            #pragma unroll 8
            for (int d = 0; d < HDIM; ++d) {
                float ed = emb_s[d], hd = hv_s[d];
                gir += ed * g_WihT[d * G3 + c];
                giz += ed * g_WihT[d * G3 + 64 + c];
                gin += ed * g_WihT[d * G3 + 128 + c];
                ghr += hd * g_WhhT[d * G3 + c];
                ghz += hd * g_WhhT[d * G3 + 64 + c];
                ghn += hd * g_WhhT[d * G3 + 128 + c];
            }
            float r = fsigmoid(gir + ghr);
            float z = fsigmoid(giz + ghz);
            float n = ftanh(gin + r * ghn);
            float hn = (1.0f - z) * n + z * hv_s[c];
            g_h[i * HDIM + c] = hn;
            hn_s[c] = hn;
        }
        __syncthreads();

        if (t < HDIM) {
            int c = t;
            float hp = b_pool[c];
            #pragma unroll 8
            for (int d = 0; d < HDIM; ++d)
                hp += hn_s[d] * W_pool[(HDIM + d) * HDIM + c];
            ((float*)g_hp2[step + 1])[hp_scalar_idx(i, c)] = hp;
        }

        // ---- grid barrier (skip after last step) ----
        if (step == PRE - 1) break;
        __syncthreads();
        if (t == 0) {
            __threadfence();   // release: u/hp stores visible GPU-wide
            unsigned target = (unsigned)BATCH * (unsigned)(step + 1);
            unsigned old = atomicAdd(&g_bar_cnt, 1u);
            if (old + 1u == target) {
                atomicExch(&g_bar_rel, (unsigned)(step + 1));
            } else {
                while (atomicAdd(&g_bar_rel, 0u) < (unsigned)(step + 1))
                    __nanosleep(64);
            }
            __threadfence();
        }
        __syncthreads();
    }
}

// ---------------------------------------------------------------------------
extern "C" void kernel_launch(void* const* d_in, const int* in_sizes, int n_in,
                              void* d_out, int out_size)
{
    const float* hidden = (const float*)d_in[0];
    const float* gt     = (const float*)d_in[1];
    const float* W_emb  = (const float*)d_in[2];
    const float* b_emb  = (const float*)d_in[3];
    const float* W_ih   = (const float*)d_in[4];
    const float* W_hh   = (const float*)d_in[5];
    const float* b_ih   = (const float*)d_in[6];
    const float* b_hh   = (const float*)d_in[7];
    const float* W_pos  = (const float*)d_in[8];
    const float* b_pos  = (const float*)d_in[9];
    const float* W_rel  = (const float*)d_in[10];
    const float* b_rel  = (const float*)d_in[11];
    const float* W_pool = (const float*)d_in[12];
    const float* b_pool = (const float*)d_in[13];
    float* out = (float*)d_out;

    init_kernel<<<BATCH + G3 + 32, 64>>>(hidden, gt, W_ih, W_hh, W_rel, W_pool, b_pool, out);
    decode_kernel<<<BATCH, 128>>>(b_rel, W_emb, b_emb, b_ih, b_hh,
                                  W_pos, b_pos, W_rel, W_pool, b_pool, out);
}

// round 9
// speedup vs baseline: 1.2530x; 1.0307x over previous
#include <cuda_runtime.h>
#include <math.h>
#include <stdint.h>

// Problem constants
#define BATCH 512
#define HDIM  64
#define OBS   8
#define PRE   12
#define G3    192   // 3*H
#define NBUF  (PRE + 1)

// Scratch (device globals — no allocation allowed)
__device__ float  g_h[BATCH * HDIM];                 // GRU hidden state (block-private)
// u per-step buffers: [step][(j>>3)*256 + (kt*4+tig)*8 + (j&7)] = {u[j][k], u[j][k+4]}
__device__ float2 g_u2[NBUF][(BATCH / 8) * 32 * 8];
// hpart per-step buffers: [step][(j>>3)*256 + cp*8 + (j&7)] = {hp[j][2cp], hp[j][2cp+1]}
__device__ float2 g_hp2[NBUF][(BATCH / 8) * 32 * 8];
__device__ float  g_WihT[HDIM * G3];                 // W_ih transposed [d][g]
__device__ float  g_WhhT[HDIM * G3];                 // W_hh transposed [d][g]
// B fragments: [(ct*4+ktp)*32 + lane] = {B(2ktp).x, B(2ktp).y, B(2ktp+1).x, B(2ktp+1).y}
__device__ uint4  g_B4[32 * 32];
// grid barrier state
__device__ unsigned g_bar_cnt;
__device__ unsigned g_bar_rel;

__device__ __forceinline__ uint32_t f2tf32(float x) {
    uint32_t u;
    asm("cvt.rna.tf32.f32 %0, %1;" : "=r"(u) : "f"(x));
    return u;
}

__device__ __forceinline__ void mma_tf32(float* d,
                                         const uint32_t* a,
                                         uint32_t b0, uint32_t b1) {
    asm volatile("mma.sync.aligned.m16n8k8.row.col.f32.tf32.tf32.f32 "
                 "{%0,%1,%2,%3}, {%4,%5,%6,%7}, {%8,%9}, {%0,%1,%2,%3};"
                 : "+f"(d[0]), "+f"(d[1]), "+f"(d[2]), "+f"(d[3])
                 : "r"(a[0]), "r"(a[1]), "r"(a[2]), "r"(a[3]), "r"(b0), "r"(b1));
}

__device__ __forceinline__ float fsigmoid(float x) {
    return 1.0f / (1.0f + __expf(-x));
}
__device__ __forceinline__ float ftanh(float x) {
    return 2.0f / (1.0f + __expf(-2.0f * x)) - 1.0f;
}

// scalar index into the float2 u/hp layouts, viewed as float
__device__ __forceinline__ int u_scalar_idx(int j, int k) {
    int kt = k >> 3, tig = k & 3, s = (k >> 2) & 1;
    return (j >> 3) * 512 + (kt * 4 + tig) * 16 + (j & 7) * 2 + s;
}
__device__ __forceinline__ int hp_scalar_idx(int j, int c) {
    return (j >> 3) * 512 + (c >> 1) * 16 + (j & 7) * 2 + (c & 1);
}

// ---------------------------------------------------------------------------
// Init: copy group_track into out, build u/hp (buffer 0), zero GRU h and
// barrier state, transpose W_ih / W_hh, precompute B fragments.
// Grid: BATCH + G3 + 32 blocks x 64 threads.
// ---------------------------------------------------------------------------
__global__ void init_kernel(const float* __restrict__ hidden,
                            const float* __restrict__ gt,
                            const float* __restrict__ W_ih,
                            const float* __restrict__ W_hh,
                            const float* __restrict__ W_rel,
                            const float* __restrict__ W_pool,
                            const float* __restrict__ b_pool,
                            float* __restrict__ out)
{
    int bid = blockIdx.x;
    int c = threadIdx.x;
    if (bid == 0 && c == 0) { g_bar_cnt = 0u; g_bar_rel = 0u; }
    if (bid < BATCH) {
        int i = bid;
        // copy observed track: out[i, 0:8, :]
        if (c < 2 * OBS) out[i * 2 * (OBS + PRE) + c] = gt[i * 2 * OBS + c];
        // u (buffer 0) from last observed position
        float px = gt[i * 2 * OBS + 2 * (OBS - 1) + 0];
        float py = gt[i * 2 * OBS + 2 * (OBS - 1) + 1];
        ((float*)g_u2[0])[u_scalar_idx(i, c)] = px * W_rel[c] + py * W_rel[HDIM + c];
        // hp (buffer 0) from hidden_state
        float acc = b_pool[c];
        #pragma unroll 8
        for (int d = 0; d < HDIM; ++d)
            acc += hidden[i * HDIM + d] * W_pool[(HDIM + d) * HDIM + c];
        ((float*)g_hp2[0])[hp_scalar_idx(i, c)] = acc;
        g_h[i * HDIM + c] = 0.0f;
    } else if (bid < BATCH + G3) {
        int g = bid - BATCH;   // 0..191
        int d = c;             // 0..63
        g_WihT[d * G3 + g] = W_ih[g * HDIM + d];
        g_WhhT[d * G3 + g] = W_hh[g * HDIM + d];
    } else if (c < 32) {
        // B fragment precompute for one (ct, ktp): covers kt = 2ktp, 2ktp+1
        int q = bid - (BATCH + G3);   // 0..31
        int ktp = q & 3, ct = q >> 2;
        int tig = c & 3, gid = c >> 2;
        int cc = ct * 8 + gid;
        int ka = (2 * ktp) * 8 + tig;
        int kb = (2 * ktp + 1) * 8 + tig;
        uint32_t b0 = f2tf32(W_pool[ka * HDIM + cc]);
        uint32_t b1 = f2tf32(W_pool[(ka + 4) * HDIM + cc]);
        uint32_t b2 = f2tf32(W_pool[kb * HDIM + cc]);
        uint32_t b3 = f2tf32(W_pool[(kb + 4) * HDIM + cc]);
        g_B4[q * 32 + c] = make_uint4(b0, b1, b2, b3);
    }
}

// ---------------------------------------------------------------------------
// Persistent fused decoder: block = one agent i, loops over all 12 steps with
// a hand-rolled grid barrier between steps (all 512 blocks co-resident:
// 128 regs x 128 thr -> 4 blocks/SM x 148 SMs = 592 slots).
// Spool mainloop: per 32-j tile, ct columns processed in PAIRS so that FOUR
// independent MMA accumulator chains (2 jt x 2 ct) interleave at issue,
// doubling ILP over the previous 2-chain version (latency-bound fix).
// Grid: 512 blocks x 128 threads.
// ---------------------------------------------------------------------------
__global__ void __launch_bounds__(128, 4) decode_kernel(
    const float* __restrict__ b_rel,
    const float* __restrict__ W_emb, const float* __restrict__ b_emb,
    const float* __restrict__ b_ih,  const float* __restrict__ b_hh,
    const float* __restrict__ W_pos, const float* __restrict__ b_pos,
    const float* __restrict__ W_rel, const float* __restrict__ W_pool,
    const float* __restrict__ b_pool, float* __restrict__ out)
{
    __shared__ float ar_s[HDIM];      // b_rel[k] - u_i[k]
    __shared__ float red_s[4][HDIM];  // cross-warp max reduction
    __shared__ float pooled_s[HDIM];
    __shared__ float pos_s[2];
    __shared__ float emb_s[HDIM];
    __shared__ float hv_s[HDIM];
    __shared__ float hn_s[HDIM];

    int i = blockIdx.x;
    int t = threadIdx.x;
    int w = t >> 5, l = t & 31;
    int gid = l >> 2, tig = l & 3;

    #pragma unroll 1
    for (int step = 0; step < PRE; ++step) {
        const float2* __restrict__ u2r  = g_u2[step];
        const float2* __restrict__ hp2r = g_hp2[step];

        if (t < HDIM)
            ar_s[t] = b_rel[t] - ((const float*)u2r)[u_scalar_idx(i, t)];
        __syncthreads();

        float mx[8][2];
        #pragma unroll
        for (int ct = 0; ct < 8; ++ct) { mx[ct][0] = 0.0f; mx[ct][1] = 0.0f; }  // relu => max>=0

        for (int p = 0; p < 4; ++p) {
            int jb = p * 128 + w * 32;
            int rb = (jb >> 3) * 256;   // float2 row-block base (8 rows per 256)
            int r1 = rb + 512;          // second jtile

            // A fragments: e = relu(u_j + (b_rel - u_i)), tf32, 2 jtiles x 8 ktiles
            uint32_t afr[2][8][4];
            #pragma unroll
            for (int jt = 0; jt < 2; ++jt) {
                int r0 = rb + jt * 512;
                #pragma unroll
                for (int kt = 0; kt < 8; ++kt) {
                    int k0 = kt * 8 + tig;
                    float arx = ar_s[k0], ary = ar_s[k0 + 4];
                    float2 v0 = u2r[r0 + (kt * 4 + tig) * 8 + gid];
                    float2 v1 = u2r[r0 + 256 + (kt * 4 + tig) * 8 + gid];
                    afr[jt][kt][0] = f2tf32(fmaxf(v0.x + arx, 0.0f));
                    afr[jt][kt][1] = f2tf32(fmaxf(v1.x + arx, 0.0f));
                    afr[jt][kt][2] = f2tf32(fmaxf(v0.y + ary, 0.0f));
                    afr[jt][kt][3] = f2tf32(fmaxf(v1.y + ary, 0.0f));
                }
            }

            // ct pairs: 4 independent accumulator chains per iteration
            #pragma unroll
            for (int ctp = 0; ctp < 4; ++ctp) {
                int ct0 = 2 * ctp, ct1 = 2 * ctp + 1;
                // C init = hpart fragments (batched: 8 independent LDG.64)
                float2 h00 = hp2r[rb + (ct0 * 4 + tig) * 8 + gid];
                float2 h01 = hp2r[rb + 256 + (ct0 * 4 + tig) * 8 + gid];
                float2 h02 = hp2r[r1 + (ct0 * 4 + tig) * 8 + gid];
                float2 h03 = hp2r[r1 + 256 + (ct0 * 4 + tig) * 8 + gid];
                float2 h10 = hp2r[rb + (ct1 * 4 + tig) * 8 + gid];
                float2 h11 = hp2r[rb + 256 + (ct1 * 4 + tig) * 8 + gid];
                float2 h12 = hp2r[r1 + (ct1 * 4 + tig) * 8 + gid];
                float2 h13 = hp2r[r1 + 256 + (ct1 * 4 + tig) * 8 + gid];
                float d00[4] = {h00.x, h00.y, h01.x, h01.y};   // jt0, ct0
                float d01[4] = {h10.x, h10.y, h11.x, h11.y};   // jt0, ct1
                float d10[4] = {h02.x, h02.y, h03.x, h03.y};   // jt1, ct0
                float d11[4] = {h12.x, h12.y, h13.x, h13.y};   // jt1, ct1

                #pragma unroll
                for (int ktp = 0; ktp < 4; ++ktp) {
                    uint4 B0 = g_B4[(ct0 * 4 + ktp) * 32 + l];
                    uint4 B1 = g_B4[(ct1 * 4 + ktp) * 32 + l];
                    // 8 MMAs: 4 independent chains, two k-steps each
                    mma_tf32(d00, afr[0][2 * ktp],     B0.x, B0.y);
                    mma_tf32(d01, afr[0][2 * ktp],     B1.x, B1.y);
                    mma_tf32(d10, afr[1][2 * ktp],     B0.x, B0.y);
                    mma_tf32(d11, afr[1][2 * ktp],     B1.x, B1.y);
                    mma_tf32(d00, afr[0][2 * ktp + 1], B0.z, B0.w);
                    mma_tf32(d01, afr[0][2 * ktp + 1], B1.z, B1.w);
                    mma_tf32(d10, afr[1][2 * ktp + 1], B0.z, B0.w);
                    mma_tf32(d11, afr[1][2 * ktp + 1], B1.z, B1.w);
                }
                mx[ct0][0] = fmaxf(mx[ct0][0], fmaxf(fmaxf(d00[0], d00[2]), fmaxf(d10[0], d10[2])));
                mx[ct0][1] = fmaxf(mx[ct0][1], fmaxf(fmaxf(d00[1], d00[3]), fmaxf(d10[1], d10[3])));
                mx[ct1][0] = fmaxf(mx[ct1][0], fmaxf(fmaxf(d01[0], d01[2]), fmaxf(d11[0], d11[2])));
                mx[ct1][1] = fmaxf(mx[ct1][1], fmaxf(fmaxf(d01[1], d01[3]), fmaxf(d11[1], d11[3])));
            }
        }

        // Reduce across lane groups (gid), write per-warp result
        #pragma unroll
        for (int ct = 0; ct < 8; ++ct) {
            #pragma unroll
            for (int pp = 0; pp < 2; ++pp) {
                float v = mx[ct][pp];
                v = fmaxf(v, __shfl_xor_sync(0xffffffffu, v, 4));
                v = fmaxf(v, __shfl_xor_sync(0xffffffffu, v, 8));
                v = fmaxf(v, __shfl_xor_sync(0xffffffffu, v, 16));
                if (gid == 0) red_s[w][ct * 8 + 2 * tig + pp] = v;
            }
        }
        __syncthreads();
        if (t < HDIM)
            pooled_s[t] = fmaxf(fmaxf(red_s[0][t], red_s[1][t]), fmaxf(red_s[2][t], red_s[3][t]));
        __syncthreads();

        // ---- update tail ----
        if (w == 0) {
            float p0 = pooled_s[l], p1 = pooled_s[l + 32];
            float px = p0 * W_pos[l * 2 + 0] + p1 * W_pos[(l + 32) * 2 + 0];
            float py = p0 * W_pos[l * 2 + 1] + p1 * W_pos[(l + 32) * 2 + 1];
            #pragma unroll
            for (int s = 16; s; s >>= 1) {
                px += __shfl_xor_sync(0xffffffffu, px, s);
                py += __shfl_xor_sync(0xffffffffu, py, s);
            }
            if (l == 0) {
                px += b_pos[0]; py += b_pos[1];
                out[i * 2 * (OBS + PRE) + (OBS + step) * 2 + 0] = px;
                out[i * 2 * (OBS + PRE) + (OBS + step) * 2 + 1] = py;
                pos_s[0] = px; pos_s[1] = py;
            }
        }
        __syncthreads();

        float px = pos_s[0], py = pos_s[1];
        if (t < HDIM) {
            // next-step u (fresh buffer: step+1)
            ((float*)g_u2[step + 1])[u_scalar_idx(i, t)] = px * W_rel[t] + py * W_rel[HDIM + t];
            // emb; stage h
            emb_s[t] = px * W_emb[t] + py * W_emb[HDIM + t] + b_emb[t];
            hv_s[t]  = g_h[i * HDIM + t];
        }
        __syncthreads();

        if (t < HDIM) {
            int c = t;
            float gir = b_ih[c], giz = b_ih[64 + c], gin = b_ih[128 + c];
            float ghr = b_hh[c], ghz = b_hh[64 + c], ghn = b_hh[128 + c];
            #pragma unroll 8
            for (int d = 0; d < HDIM; ++d) {
                float ed = emb_s[d], hd = hv_s[d];
                gir += ed * g_WihT[d * G3 + c];
                giz += ed * g_WihT[d * G3 + 64 + c];
                gin += ed * g_WihT[d * G3 + 128 + c];
                ghr += hd * g_WhhT[d * G3 + c];
                ghz += hd * g_WhhT[d * G3 + 64 + c];
                ghn += hd * g_WhhT[d * G3 + 128 + c];
            }
            float r = fsigmoid(gir + ghr);
            float z = fsigmoid(giz + ghz);
            float n = ftanh(gin + r * ghn);
            float hn = (1.0f - z) * n + z * hv_s[c];
            g_h[i * HDIM + c] = hn;
            hn_s[c] = hn;
        }
        __syncthreads();

        if (t < HDIM) {
            int c = t;
            float hp = b_pool[c];
            #pragma unroll 8
            for (int d = 0; d < HDIM; ++d)
                hp += hn_s[d] * W_pool[(HDIM + d) * HDIM + c];
            ((float*)g_hp2[step + 1])[hp_scalar_idx(i, c)] = hp;
        }

        // ---- grid barrier (skip after last step) ----
        if (step == PRE - 1) break;
        __syncthreads();
        if (t == 0) {
            __threadfence();   // release: u/hp stores visible GPU-wide
            unsigned target = (unsigned)BATCH * (unsigned)(step + 1);
            unsigned old = atomicAdd(&g_bar_cnt, 1u);
            if (old + 1u == target) {
                atomicExch(&g_bar_rel, (unsigned)(step + 1));
            } else {
                while (atomicAdd(&g_bar_rel, 0u) < (unsigned)(step + 1))
                    __nanosleep(64);
            }
            __threadfence();
        }
        __syncthreads();
    }
}

// ---------------------------------------------------------------------------
extern "C" void kernel_launch(void* const* d_in, const int* in_sizes, int n_in,
                              void* d_out, int out_size)
{
    const float* hidden = (const float*)d_in[0];
    const float* gt     = (const float*)d_in[1];
    const float* W_emb  = (const float*)d_in[2];
    const float* b_emb  = (const float*)d_in[3];
    const float* W_ih   = (const float*)d_in[4];
    const float* W_hh   = (const float*)d_in[5];
    const float* b_ih   = (const float*)d_in[6];
    const float* b_hh   = (const float*)d_in[7];
    const float* W_pos  = (const float*)d_in[8];
    const float* b_pos  = (const float*)d_in[9];
    const float* W_rel  = (const float*)d_in[10];
    const float* b_rel  = (const float*)d_in[11];
    const float* W_pool = (const float*)d_in[12];
    const float* b_pool = (const float*)d_in[13];
    float* out = (float*)d_out;

    init_kernel<<<BATCH + G3 + 32, 64>>>(hidden, gt, W_ih, W_hh, W_rel, W_pool, b_pool, out);
    decode_kernel<<<BATCH, 128>>>(b_rel, W_emb, b_emb, b_ih, b_hh,
                                  W_pos, b_pos, W_rel, W_pool, b_pool, out);
}

// round 10
// speedup vs baseline: 1.5891x; 1.2683x over previous
#include <cuda_runtime.h>
#include <cuda_fp16.h>
#include <math.h>
#include <stdint.h>

// Problem constants
#define BATCH 512
#define HDIM  64
#define OBS   8
#define PRE   12
#define G3    192   // 3*H
#define NBUF  (PRE + 1)

// Scratch (device globals — no allocation allowed)
__device__ float   g_h[BATCH * HDIM];                // GRU hidden state (block-private)
// u per-step buffers, f16 pairs: [step][(j>>3)*256 + kp*8 + (j&7)] = half2{u[j][2kp], u[j][2kp+1]}
__device__ __half2 g_uh[NBUF][(BATCH / 8) * 32 * 8];
// hpart per-step buffers (f32): [step][(j>>3)*256 + cp*8 + (j&7)] = {hp[j][2cp], hp[j][2cp+1]}
__device__ float2  g_hp2[NBUF][(BATCH / 8) * 32 * 8];
__device__ float   g_WihT[HDIM * G3];                // W_ih transposed [d][g]
__device__ float   g_WhhT[HDIM * G3];                // W_hh transposed [d][g]
// f16 B fragments for m16n8k16: [(ctp*4 + kt16)*32 + lane] = {b0_ct0, b1_ct0, b0_ct1, b1_ct1}
__device__ uint4   g_B4[16 * 32];
// grid barrier state
__device__ unsigned g_bar_cnt;
__device__ unsigned g_bar_rel;

__device__ __forceinline__ uint32_t h2u(__half2 h) {
    return *reinterpret_cast<uint32_t*>(&h);
}

// m16n8k16 f16 MMA, f32 accumulate
__device__ __forceinline__ void mma_f16(float* d,
                                        uint32_t a0, uint32_t a1, uint32_t a2, uint32_t a3,
                                        uint32_t b0, uint32_t b1) {
    asm volatile("mma.sync.aligned.m16n8k16.row.col.f32.f16.f16.f32 "
                 "{%0,%1,%2,%3}, {%4,%5,%6,%7}, {%8,%9}, {%0,%1,%2,%3};"
                 : "+f"(d[0]), "+f"(d[1]), "+f"(d[2]), "+f"(d[3])
                 : "r"(a0), "r"(a1), "r"(a2), "r"(a3), "r"(b0), "r"(b1));
}

__device__ __forceinline__ float fsigmoid(float x) {
    return 1.0f / (1.0f + __expf(-x));
}
__device__ __forceinline__ float ftanh(float x) {
    return 2.0f / (1.0f + __expf(-2.0f * x)) - 1.0f;
}

// index helpers (half2 / float2 element granularity)
__device__ __forceinline__ int uh_idx(int j, int kp) {     // kp in [0,32)
    return (j >> 3) * 256 + kp * 8 + (j & 7);
}
__device__ __forceinline__ int hp_scalar_idx(int j, int c) {
    return (j >> 3) * 512 + (c >> 1) * 16 + (j & 7) * 2 + (c & 1);
}

// ---------------------------------------------------------------------------
// Init: copy group_track into out, build u(f16)/hp (buffer 0), zero GRU h and
// barrier state, transpose W_ih / W_hh, precompute f16 B fragments.
// Grid: BATCH + G3 + 16 blocks x 64 threads.
// ---------------------------------------------------------------------------
__global__ void init_kernel(const float* __restrict__ hidden,
                            const float* __restrict__ gt,
                            const float* __restrict__ W_ih,
                            const float* __restrict__ W_hh,
                            const float* __restrict__ W_rel,
                            const float* __restrict__ W_pool,
                            const float* __restrict__ b_pool,
                            float* __restrict__ out)
{
    int bid = blockIdx.x;
    int c = threadIdx.x;
    if (bid == 0 && c == 0) { g_bar_cnt = 0u; g_bar_rel = 0u; }
    if (bid < BATCH) {
        int i = bid;
        // copy observed track: out[i, 0:8, :]
        if (c < 2 * OBS) out[i * 2 * (OBS + PRE) + c] = gt[i * 2 * OBS + c];
        float px = gt[i * 2 * OBS + 2 * (OBS - 1) + 0];
        float py = gt[i * 2 * OBS + 2 * (OBS - 1) + 1];
        if (c < 32) {
            // u pair (buffer 0)
            float u0 = px * W_rel[2 * c]     + py * W_rel[HDIM + 2 * c];
            float u1 = px * W_rel[2 * c + 1] + py * W_rel[HDIM + 2 * c + 1];
            g_uh[0][uh_idx(i, c)] = __floats2half2_rn(u0, u1);
        }
        // hp (buffer 0) from hidden_state
        float acc = b_pool[c];
        #pragma unroll 8
        for (int d = 0; d < HDIM; ++d)
            acc += hidden[i * HDIM + d] * W_pool[(HDIM + d) * HDIM + c];
        ((float*)g_hp2[0])[hp_scalar_idx(i, c)] = acc;
        g_h[i * HDIM + c] = 0.0f;
    } else if (bid < BATCH + G3) {
        int g = bid - BATCH;   // 0..191
        int d = c;             // 0..63
        g_WihT[d * G3 + g] = W_ih[g * HDIM + d];
        g_WhhT[d * G3 + g] = W_hh[g * HDIM + d];
    } else if (c < 32) {
        // f16 B fragments for one (ctp, kt16)
        int q = bid - (BATCH + G3);   // 0..15
        int kt16 = q & 3, ctp = q >> 2;
        int tig = c & 3, gid = c >> 2;
        int k0 = kt16 * 16;
        int c0 = ctp * 16 + gid;      // ct0 column
        int c1 = c0 + 8;              // ct1 column
        uint32_t b00 = h2u(__floats2half2_rn(W_pool[(k0 + 2 * tig) * HDIM + c0],
                                             W_pool[(k0 + 2 * tig + 1) * HDIM + c0]));
        uint32_t b10 = h2u(__floats2half2_rn(W_pool[(k0 + 8 + 2 * tig) * HDIM + c0],
                                             W_pool[(k0 + 8 + 2 * tig + 1) * HDIM + c0]));
        uint32_t b01 = h2u(__floats2half2_rn(W_pool[(k0 + 2 * tig) * HDIM + c1],
                                             W_pool[(k0 + 2 * tig + 1) * HDIM + c1]));
        uint32_t b11 = h2u(__floats2half2_rn(W_pool[(k0 + 8 + 2 * tig) * HDIM + c1],
                                             W_pool[(k0 + 8 + 2 * tig + 1) * HDIM + c1]));
        g_B4[q * 32 + c] = make_uint4(b00, b10, b01, b11);
    }
}

// ---------------------------------------------------------------------------
// Persistent fused decoder (f16 MMA): block = one agent i, 12 steps, grid
// barrier between steps (all 512 blocks co-resident). Spool: per 32-j tile,
// e built with HADD2/HMAX2 straight into packed f16 A fragments; m16n8k16
// halves MMA count; 4 independent chains per ct-pair; hp (f32) as C-init.
// Grid: 512 blocks x 128 threads.
// ---------------------------------------------------------------------------
__global__ void __launch_bounds__(128, 4) decode_kernel(
    const float* __restrict__ b_rel,
    const float* __restrict__ W_emb, const float* __restrict__ b_emb,
    const float* __restrict__ b_ih,  const float* __restrict__ b_hh,
    const float* __restrict__ W_pos, const float* __restrict__ b_pos,
    const float* __restrict__ W_rel, const float* __restrict__ W_pool,
    const float* __restrict__ b_pool, float* __restrict__ out)
{
    __shared__ __half2 ar_s[32];      // pair {b_rel - u_i} at kp
    __shared__ float red_s[4][HDIM];  // cross-warp max reduction
    __shared__ float pooled_s[HDIM];
    __shared__ float pos_s[2];
    __shared__ float emb_s[HDIM];
    __shared__ float hv_s[HDIM];
    __shared__ float hn_s[HDIM];

    int i = blockIdx.x;
    int t = threadIdx.x;
    int w = t >> 5, l = t & 31;
    int gid = l >> 2, tig = l & 3;

    #pragma unroll 1
    for (int step = 0; step < PRE; ++step) {
        const __half2* __restrict__ uhr = g_uh[step];
        const float2*  __restrict__ hp2r = g_hp2[step];

        if (t < 32) {
            float2 ui = __half22float2(uhr[uh_idx(i, t)]);
            ar_s[t] = __floats2half2_rn(b_rel[2 * t] - ui.x, b_rel[2 * t + 1] - ui.y);
        }
        __syncthreads();

        float mx[8][2];
        #pragma unroll
        for (int ct = 0; ct < 8; ++ct) { mx[ct][0] = 0.0f; mx[ct][1] = 0.0f; }  // relu => max>=0

        for (int p = 0; p < 4; ++p) {
            int jb = p * 128 + w * 32;
            int rb = (jb >> 3) * 256;   // half2/float2 row-block base (8 rows per 256)
            int r1 = rb + 512;          // second jtile (+16 rows)

            // A fragments: e = hmax2(hadd2(u_j, ar), 0), packed f16, 2 jt x 4 kt16
            __half2 zero2 = __float2half2_rn(0.0f);
            uint32_t afr[2][4][4];
            #pragma unroll
            for (int kt = 0; kt < 4; ++kt) {
                int kp0 = kt * 8 + tig;     // cols 2kp0, 2kp0+1
                int kp1 = kp0 + 4;          // cols +8
                __half2 ar0 = ar_s[kp0], ar1 = ar_s[kp1];
                #pragma unroll
                for (int jt = 0; jt < 2; ++jt) {
                    int r0 = rb + jt * 512;
                    __half2 v00 = uhr[r0 + kp0 * 8 + gid];          // row gid
                    __half2 v10 = uhr[r0 + 256 + kp0 * 8 + gid];    // row gid+8
                    __half2 v01 = uhr[r0 + kp1 * 8 + gid];
                    __half2 v11 = uhr[r0 + 256 + kp1 * 8 + gid];
                    afr[jt][kt][0] = h2u(__hmax2(__hadd2(v00, ar0), zero2));
                    afr[jt][kt][1] = h2u(__hmax2(__hadd2(v10, ar0), zero2));
                    afr[jt][kt][2] = h2u(__hmax2(__hadd2(v01, ar1), zero2));
                    afr[jt][kt][3] = h2u(__hmax2(__hadd2(v11, ar1), zero2));
                }
            }

            // ct pairs: 4 independent accumulator chains, 4 k16-steps each
            #pragma unroll
            for (int ctp = 0; ctp < 4; ++ctp) {
                int ct0 = 2 * ctp, ct1 = 2 * ctp + 1;
                // C init = hpart fragments (f32, batched LDG.64)
                float2 h00 = hp2r[rb + (ct0 * 4 + tig) * 8 + gid];
                float2 h01 = hp2r[rb + 256 + (ct0 * 4 + tig) * 8 + gid];
                float2 h02 = hp2r[r1 + (ct0 * 4 + tig) * 8 + gid];
                float2 h03 = hp2r[r1 + 256 + (ct0 * 4 + tig) * 8 + gid];
                float2 h10 = hp2r[rb + (ct1 * 4 + tig) * 8 + gid];
                float2 h11 = hp2r[rb + 256 + (ct1 * 4 + tig) * 8 + gid];
                float2 h12 = hp2r[r1 + (ct1 * 4 + tig) * 8 + gid];
                float2 h13 = hp2r[r1 + 256 + (ct1 * 4 + tig) * 8 + gid];
                float d00[4] = {h00.x, h00.y, h01.x, h01.y};   // jt0, ct0
                float d01[4] = {h10.x, h10.y, h11.x, h11.y};   // jt0, ct1
                float d10[4] = {h02.x, h02.y, h03.x, h03.y};   // jt1, ct0
                float d11[4] = {h12.x, h12.y, h13.x, h13.y};   // jt1, ct1

                #pragma unroll
                for (int kt = 0; kt < 4; ++kt) {
                    uint4 B = g_B4[(ctp * 4 + kt) * 32 + l];
                    mma_f16(d00, afr[0][kt][0], afr[0][kt][1], afr[0][kt][2], afr[0][kt][3], B.x, B.y);
                    mma_f16(d01, afr[0][kt][0], afr[0][kt][1], afr[0][kt][2], afr[0][kt][3], B.z, B.w);
                    mma_f16(d10, afr[1][kt][0], afr[1][kt][1], afr[1][kt][2], afr[1][kt][3], B.x, B.y);
                    mma_f16(d11, afr[1][kt][0], afr[1][kt][1], afr[1][kt][2], afr[1][kt][3], B.z, B.w);
                }
                mx[ct0][0] = fmaxf(mx[ct0][0], fmaxf(fmaxf(d00[0], d00[2]), fmaxf(d10[0], d10[2])));
                mx[ct0][1] = fmaxf(mx[ct0][1], fmaxf(fmaxf(d00[1], d00[3]), fmaxf(d10[1], d10[3])));
                mx[ct1][0] = fmaxf(mx[ct1][0], fmaxf(fmaxf(d01[0], d01[2]), fmaxf(d11[0], d11[2])));
                mx[ct1][1] = fmaxf(mx[ct1][1], fmaxf(fmaxf(d01[1], d01[3]), fmaxf(d11[1], d11[3])));
            }
        }

        // Reduce across lane groups (gid), write per-warp result
        #pragma unroll
        for (int ct = 0; ct < 8; ++ct) {
            #pragma unroll
            for (int pp = 0; pp < 2; ++pp) {
                float v = mx[ct][pp];
                v = fmaxf(v, __shfl_xor_sync(0xffffffffu, v, 4));
                v = fmaxf(v, __shfl_xor_sync(0xffffffffu, v, 8));
                v = fmaxf(v, __shfl_xor_sync(0xffffffffu, v, 16));
                if (gid == 0) red_s[w][ct * 8 + 2 * tig + pp] = v;
            }
        }
        __syncthreads();
        if (t < HDIM)
            pooled_s[t] = fmaxf(fmaxf(red_s[0][t], red_s[1][t]), fmaxf(red_s[2][t], red_s[3][t]));
        __syncthreads();

        // ---- update tail ----
        if (w == 0) {
            float p0 = pooled_s[l], p1 = pooled_s[l + 32];
            float px = p0 * W_pos[l * 2 + 0] + p1 * W_pos[(l + 32) * 2 + 0];
            float py = p0 * W_pos[l * 2 + 1] + p1 * W_pos[(l + 32) * 2 + 1];
            #pragma unroll
            for (int s = 16; s; s >>= 1) {
                px += __shfl_xor_sync(0xffffffffu, px, s);
                py += __shfl_xor_sync(0xffffffffu, py, s);
            }
            if (l == 0) {
                px += b_pos[0]; py += b_pos[1];
                out[i * 2 * (OBS + PRE) + (OBS + step) * 2 + 0] = px;
                out[i * 2 * (OBS + PRE) + (OBS + step) * 2 + 1] = py;
                pos_s[0] = px; pos_s[1] = py;
            }
        }
        __syncthreads();

        float px = pos_s[0], py = pos_s[1];
        if (t < 32) {
            // next-step u pair (f16, fresh buffer: step+1)
            float u0 = px * W_rel[2 * t]     + py * W_rel[HDIM + 2 * t];
            float u1 = px * W_rel[2 * t + 1] + py * W_rel[HDIM + 2 * t + 1];
            g_uh[step + 1][uh_idx(i, t)] = __floats2half2_rn(u0, u1);
        }
        if (t < HDIM) {
            // emb; stage h
            emb_s[t] = px * W_emb[t] + py * W_emb[HDIM + t] + b_emb[t];
            hv_s[t]  = g_h[i * HDIM + t];
        }
        __syncthreads();

        if (t < HDIM) {
            int c = t;
            float gir = b_ih[c], giz = b_ih[64 + c], gin = b_ih[128 + c];
            float ghr = b_hh[c], ghz = b_hh[64 + c], ghn = b_hh[128 + c];
            #pragma unroll 8
            for (int d = 0; d < HDIM; ++d) {
                float ed = emb_s[d], hd = hv_s[d];
                gir += ed * g_WihT[d * G3 + c];
                giz += ed * g_WihT[d * G3 + 64 + c];
                gin += ed * g_WihT[d * G3 + 128 + c];
                ghr += hd * g_WhhT[d * G3 + c];
                ghz += hd * g_WhhT[d * G3 + 64 + c];
                ghn += hd * g_WhhT[d * G3 + 128 + c];
            }
            float r = fsigmoid(gir + ghr);
            float z = fsigmoid(giz + ghz);
            float n = ftanh(gin + r * ghn);
            float hn = (1.0f - z) * n + z * hv_s[c];
            g_h[i * HDIM + c] = hn;
            hn_s[c] = hn;
        }
        __syncthreads();

        if (t < HDIM) {
            int c = t;
            float hp = b_pool[c];
            #pragma unroll 8
            for (int d = 0; d < HDIM; ++d)
                hp += hn_s[d] * W_pool[(HDIM + d) * HDIM + c];
            ((float*)g_hp2[step + 1])[hp_scalar_idx(i, c)] = hp;
        }

        // ---- grid barrier (skip after last step) ----
        if (step == PRE - 1) break;
        __syncthreads();
        if (t == 0) {
            __threadfence();   // release: u/hp stores visible GPU-wide
            unsigned target = (unsigned)BATCH * (unsigned)(step + 1);
            unsigned old = atomicAdd(&g_bar_cnt, 1u);
            if (old + 1u == target) {
                atomicExch(&g_bar_rel, (unsigned)(step + 1));
            } else {
                while (atomicAdd(&g_bar_rel, 0u) < (unsigned)(step + 1))
                    __nanosleep(64);
            }
            __threadfence();
        }
        __syncthreads();
    }
}

// ---------------------------------------------------------------------------
extern "C" void kernel_launch(void* const* d_in, const int* in_sizes, int n_in,
                              void* d_out, int out_size)
{
    const float* hidden = (const float*)d_in[0];
    const float* gt     = (const float*)d_in[1];
    const float* W_emb  = (const float*)d_in[2];
    const float* b_emb  = (const float*)d_in[3];
    const float* W_ih   = (const float*)d_in[4];
    const float* W_hh   = (const float*)d_in[5];
    const float* b_ih   = (const float*)d_in[6];
    const float* b_hh   = (const float*)d_in[7];
    const float* W_pos  = (const float*)d_in[8];
    const float* b_pos  = (const float*)d_in[9];
    const float* W_rel  = (const float*)d_in[10];
    const float* b_rel  = (const float*)d_in[11];
    const float* W_pool = (const float*)d_in[12];
    const float* b_pool = (const float*)d_in[13];
    float* out = (float*)d_out;

    init_kernel<<<BATCH + G3 + 16, 64>>>(hidden, gt, W_ih, W_hh, W_rel, W_pool, b_pool, out);
    decode_kernel<<<BATCH, 128>>>(b_rel, W_emb, b_emb, b_ih, b_hh,
                                  W_pos, b_pos, W_rel, W_pool, b_pool, out);
}

// round 11
// speedup vs baseline: 2.0819x; 1.3101x over previous
#include <cuda_runtime.h>
#include <cuda_fp16.h>
#include <math.h>
#include <stdint.h>

// Problem constants
#define BATCH 512
#define HDIM  64
#define OBS   8
#define PRE   12
#define G3    192   // 3*H
#define NBUF  (PRE + 1)

// Scratch (device globals — no allocation allowed)
__device__ float   g_h[BATCH * HDIM];                // GRU hidden state (block-private)
// u per-step buffers, f16 pairs: [step][(j>>3)*256 + kp*8 + (j&7)] = half2{u[j][2kp], u[j][2kp+1]}
__device__ __half2 g_uh[NBUF][(BATCH / 8) * 32 * 8];
// hpart per-step buffers, f16 pairs: [step][(j>>3)*256 + cp*8 + (j&7)] = half2{hp[j][2cp], hp[j][2cp+1]}
__device__ __half2 g_hph[NBUF][(BATCH / 8) * 32 * 8];
__device__ __align__(16) float g_WihT[HDIM * G3];    // W_ih transposed [d][g]
__device__ __align__(16) float g_WhhT[HDIM * G3];    // W_hh transposed [d][g]
// f16 B fragments for m16n8k16: [(ctp*4 + kt16)*32 + lane] = {b0_ct0, b1_ct0, b0_ct1, b1_ct1}
__device__ uint4   g_B4[16 * 32];
// grid barrier state
__device__ unsigned g_bar_cnt;
__device__ unsigned g_bar_rel;

__device__ __forceinline__ uint32_t h2u(__half2 h) {
    return *reinterpret_cast<uint32_t*>(&h);
}

// m16n8k16 f16 MMA, f32 accumulate
__device__ __forceinline__ void mma_f16(float* d,
                                        uint32_t a0, uint32_t a1, uint32_t a2, uint32_t a3,
                                        uint32_t b0, uint32_t b1) {
    asm volatile("mma.sync.aligned.m16n8k16.row.col.f32.f16.f16.f32 "
                 "{%0,%1,%2,%3}, {%4,%5,%6,%7}, {%8,%9}, {%0,%1,%2,%3};"
                 : "+f"(d[0]), "+f"(d[1]), "+f"(d[2]), "+f"(d[3])
                 : "r"(a0), "r"(a1), "r"(a2), "r"(a3), "r"(b0), "r"(b1));
}

__device__ __forceinline__ float fsigmoid(float x) {
    return 1.0f / (1.0f + __expf(-x));
}
__device__ __forceinline__ float ftanh(float x) {
    return 2.0f / (1.0f + __expf(-2.0f * x)) - 1.0f;
}

// index helper: half2 pair buffers (u and hp share the layout)
__device__ __forceinline__ int pair_idx(int j, int p) {   // p in [0,32)
    return (j >> 3) * 256 + p * 8 + (j & 7);
}

// ---------------------------------------------------------------------------
// Init: copy group_track into out, build u/hp (f16, buffer 0), zero GRU h and
// barrier state, transpose W_ih / W_hh, precompute f16 B fragments.
// Grid: BATCH + G3 + 16 blocks x 64 threads.
// ---------------------------------------------------------------------------
__global__ void init_kernel(const float* __restrict__ hidden,
                            const float* __restrict__ gt,
                            const float* __restrict__ W_ih,
                            const float* __restrict__ W_hh,
                            const float* __restrict__ W_rel,
                            const float* __restrict__ W_pool,
                            const float* __restrict__ b_pool,
                            float* __restrict__ out)
{
    __shared__ float tmp_s[HDIM];
    int bid = blockIdx.x;
    int c = threadIdx.x;
    if (bid == 0 && c == 0) { g_bar_cnt = 0u; g_bar_rel = 0u; }
    if (bid < BATCH) {
        int i = bid;
        // copy observed track: out[i, 0:8, :]
        if (c < 2 * OBS) out[i * 2 * (OBS + PRE) + c] = gt[i * 2 * OBS + c];
        float px = gt[i * 2 * OBS + 2 * (OBS - 1) + 0];
        float py = gt[i * 2 * OBS + 2 * (OBS - 1) + 1];
        if (c < 32) {
            float u0 = px * W_rel[2 * c]     + py * W_rel[HDIM + 2 * c];
            float u1 = px * W_rel[2 * c + 1] + py * W_rel[HDIM + 2 * c + 1];
            g_uh[0][pair_idx(i, c)] = __floats2half2_rn(u0, u1);
        }
        // hp (buffer 0) from hidden_state
        float acc = b_pool[c];
        #pragma unroll 8
        for (int d = 0; d < HDIM; ++d)
            acc += hidden[i * HDIM + d] * W_pool[(HDIM + d) * HDIM + c];
        tmp_s[c] = acc;
        g_h[i * HDIM + c] = 0.0f;
        __syncthreads();
        if (c < 32)
            g_hph[0][pair_idx(i, c)] = __floats2half2_rn(tmp_s[2 * c], tmp_s[2 * c + 1]);
    } else if (bid < BATCH + G3) {
        int g = bid - BATCH;   // 0..191
        int d = c;             // 0..63
        g_WihT[d * G3 + g] = W_ih[g * HDIM + d];
        g_WhhT[d * G3 + g] = W_hh[g * HDIM + d];
    } else if (c < 32) {
        // f16 B fragments for one (ctp, kt16)
        int q = bid - (BATCH + G3);   // 0..15
        int kt16 = q & 3, ctp = q >> 2;
        int tig = c & 3, gid = c >> 2;
        int k0 = kt16 * 16;
        int c0 = ctp * 16 + gid;      // ct0 column
        int c1 = c0 + 8;              // ct1 column
        uint32_t b00 = h2u(__floats2half2_rn(W_pool[(k0 + 2 * tig) * HDIM + c0],
                                             W_pool[(k0 + 2 * tig + 1) * HDIM + c0]));
        uint32_t b10 = h2u(__floats2half2_rn(W_pool[(k0 + 8 + 2 * tig) * HDIM + c0],
                                             W_pool[(k0 + 8 + 2 * tig + 1) * HDIM + c0]));
        uint32_t b01 = h2u(__floats2half2_rn(W_pool[(k0 + 2 * tig) * HDIM + c1],
                                             W_pool[(k0 + 2 * tig + 1) * HDIM + c1]));
        uint32_t b11 = h2u(__floats2half2_rn(W_pool[(k0 + 8 + 2 * tig) * HDIM + c1],
                                             W_pool[(k0 + 8 + 2 * tig + 1) * HDIM + c1]));
        g_B4[q * 32 + c] = make_uint4(b00, b10, b01, b11);
    }
}

// ---------------------------------------------------------------------------
// Persistent fused decoder (f16 MMA, f16 hp, float4 tail):
// block = one agent i, 12 steps, grid barrier between steps (all 512 blocks
// co-resident: 128 regs x 128 thr -> 4 blocks/SM). Spool mainloop unchanged
// from R10 except hp loads are half2. Tail: 6 GRU gate matvecs via 96
// threads x float4 LDG.128; hp production via 64 threads x float4 + reduce.
// Barrier polls with ld.global.cg (non-serializing) instead of atomics.
// Grid: 512 blocks x 128 threads.
// ---------------------------------------------------------------------------
__global__ void __launch_bounds__(128, 4) decode_kernel(
    const float* __restrict__ b_rel,
    const float* __restrict__ W_emb, const float* __restrict__ b_emb,
    const float* __restrict__ b_ih,  const float* __restrict__ b_hh,
    const float* __restrict__ W_pos, const float* __restrict__ b_pos,
    const float* __restrict__ W_rel, const float* __restrict__ W_pool,
    const float* __restrict__ b_pool, float* __restrict__ out)
{
    __shared__ __half2 ar_s[32];      // pair {b_rel - u_i} at kp
    __shared__ float red_s[4][HDIM];  // cross-warp max reduction
    __shared__ float pooled_s[HDIM];
    __shared__ float pos_s[2];
    __shared__ float emb_s[HDIM];
    __shared__ float hv_s[HDIM];
    __shared__ float hn_s[HDIM];
    __shared__ __align__(16) float gate_s[6][HDIM];
    __shared__ float4 hpr_s[16][4];

    int i = blockIdx.x;
    int t = threadIdx.x;
    int w = t >> 5, l = t & 31;
    int gid = l >> 2, tig = l & 3;

    #pragma unroll 1
    for (int step = 0; step < PRE; ++step) {
        const __half2* __restrict__ uhr = g_uh[step];
        const __half2* __restrict__ hph = g_hph[step];

        if (t < 32) {
            float2 ui = __half22float2(uhr[pair_idx(i, t)]);
            ar_s[t] = __floats2half2_rn(b_rel[2 * t] - ui.x, b_rel[2 * t + 1] - ui.y);
        }
        __syncthreads();

        float mx[8][2];
        #pragma unroll
        for (int ct = 0; ct < 8; ++ct) { mx[ct][0] = 0.0f; mx[ct][1] = 0.0f; }  // relu => max>=0

        for (int p = 0; p < 4; ++p) {
            int jb = p * 128 + w * 32;
            int rb = (jb >> 3) * 256;   // half2 row-block base (8 rows per 256)
            int r1 = rb + 512;          // second jtile (+16 rows)

            // A fragments: e = hmax2(hadd2(u_j, ar), 0), packed f16, 2 jt x 4 kt16
            __half2 zero2 = __float2half2_rn(0.0f);
            uint32_t afr[2][4][4];
            #pragma unroll
            for (int kt = 0; kt < 4; ++kt) {
                int kp0 = kt * 8 + tig;     // cols 2kp0, 2kp0+1
                int kp1 = kp0 + 4;          // cols +8
                __half2 ar0 = ar_s[kp0], ar1 = ar_s[kp1];
                #pragma unroll
                for (int jt = 0; jt < 2; ++jt) {
                    int r0 = rb + jt * 512;
                    __half2 v00 = uhr[r0 + kp0 * 8 + gid];          // row gid
                    __half2 v10 = uhr[r0 + 256 + kp0 * 8 + gid];    // row gid+8
                    __half2 v01 = uhr[r0 + kp1 * 8 + gid];
                    __half2 v11 = uhr[r0 + 256 + kp1 * 8 + gid];
                    afr[jt][kt][0] = h2u(__hmax2(__hadd2(v00, ar0), zero2));
                    afr[jt][kt][1] = h2u(__hmax2(__hadd2(v10, ar0), zero2));
                    afr[jt][kt][2] = h2u(__hmax2(__hadd2(v01, ar1), zero2));
                    afr[jt][kt][3] = h2u(__hmax2(__hadd2(v11, ar1), zero2));
                }
            }

            // ct pairs: 4 independent accumulator chains, 4 k16-steps each
            #pragma unroll
            for (int ctp = 0; ctp < 4; ++ctp) {
                int ct0 = 2 * ctp, ct1 = 2 * ctp + 1;
                // C init = hpart fragments (f16 -> f32)
                float2 h00 = __half22float2(hph[rb + (ct0 * 4 + tig) * 8 + gid]);
                float2 h01 = __half22float2(hph[rb + 256 + (ct0 * 4 + tig) * 8 + gid]);
                float2 h02 = __half22float2(hph[r1 + (ct0 * 4 + tig) * 8 + gid]);
                float2 h03 = __half22float2(hph[r1 + 256 + (ct0 * 4 + tig) * 8 + gid]);
                float2 h10 = __half22float2(hph[rb + (ct1 * 4 + tig) * 8 + gid]);
                float2 h11 = __half22float2(hph[rb + 256 + (ct1 * 4 + tig) * 8 + gid]);
                float2 h12 = __half22float2(hph[r1 + (ct1 * 4 + tig) * 8 + gid]);
                float2 h13 = __half22float2(hph[r1 + 256 + (ct1 * 4 + tig) * 8 + gid]);
                float d00[4] = {h00.x, h00.y, h01.x, h01.y};   // jt0, ct0
                float d01[4] = {h10.x, h10.y, h11.x, h11.y};   // jt0, ct1
                float d10[4] = {h02.x, h02.y, h03.x, h03.y};   // jt1, ct0
                float d11[4] = {h12.x, h12.y, h13.x, h13.y};   // jt1, ct1

                #pragma unroll
                for (int kt = 0; kt < 4; ++kt) {
                    uint4 B = g_B4[(ctp * 4 + kt) * 32 + l];
                    mma_f16(d00, afr[0][kt][0], afr[0][kt][1], afr[0][kt][2], afr[0][kt][3], B.x, B.y);
                    mma_f16(d01, afr[0][kt][0], afr[0][kt][1], afr[0][kt][2], afr[0][kt][3], B.z, B.w);
                    mma_f16(d10, afr[1][kt][0], afr[1][kt][1], afr[1][kt][2], afr[1][kt][3], B.x, B.y);
                    mma_f16(d11, afr[1][kt][0], afr[1][kt][1], afr[1][kt][2], afr[1][kt][3], B.z, B.w);
                }
                mx[ct0][0] = fmaxf(mx[ct0][0], fmaxf(fmaxf(d00[0], d00[2]), fmaxf(d10[0], d10[2])));
                mx[ct0][1] = fmaxf(mx[ct0][1], fmaxf(fmaxf(d00[1], d00[3]), fmaxf(d10[1], d10[3])));
                mx[ct1][0] = fmaxf(mx[ct1][0], fmaxf(fmaxf(d01[0], d01[2]), fmaxf(d11[0], d11[2])));
                mx[ct1][1] = fmaxf(mx[ct1][1], fmaxf(fmaxf(d01[1], d01[3]), fmaxf(d11[1], d11[3])));
            }
        }

        // Reduce across lane groups (gid), write per-warp result
        #pragma unroll
        for (int ct = 0; ct < 8; ++ct) {
            #pragma unroll
            for (int pp = 0; pp < 2; ++pp) {
                float v = mx[ct][pp];
                v = fmaxf(v, __shfl_xor_sync(0xffffffffu, v, 4));
                v = fmaxf(v, __shfl_xor_sync(0xffffffffu, v, 8));
                v = fmaxf(v, __shfl_xor_sync(0xffffffffu, v, 16));
                if (gid == 0) red_s[w][ct * 8 + 2 * tig + pp] = v;
            }
        }
        __syncthreads();
        if (t < HDIM)
            pooled_s[t] = fmaxf(fmaxf(red_s[0][t], red_s[1][t]), fmaxf(red_s[2][t], red_s[3][t]));
        __syncthreads();

        // ---- update tail ----
        if (w == 0) {
            float p0 = pooled_s[l], p1 = pooled_s[l + 32];
            float px = p0 * W_pos[l * 2 + 0] + p1 * W_pos[(l + 32) * 2 + 0];
            float py = p0 * W_pos[l * 2 + 1] + p1 * W_pos[(l + 32) * 2 + 1];
            #pragma unroll
            for (int s = 16; s; s >>= 1) {
                px += __shfl_xor_sync(0xffffffffu, px, s);
                py += __shfl_xor_sync(0xffffffffu, py, s);
            }
            if (l == 0) {
                px += b_pos[0]; py += b_pos[1];
                out[i * 2 * (OBS + PRE) + (OBS + step) * 2 + 0] = px;
                out[i * 2 * (OBS + PRE) + (OBS + step) * 2 + 1] = py;
                pos_s[0] = px; pos_s[1] = py;
            }
        }
        __syncthreads();

        float px = pos_s[0], py = pos_s[1];
        if (t < 32) {
            // next-step u pair (f16, fresh buffer: step+1)
            float u0 = px * W_rel[2 * t]     + py * W_rel[HDIM + 2 * t];
            float u1 = px * W_rel[2 * t + 1] + py * W_rel[HDIM + 2 * t + 1];
            g_uh[step + 1][pair_idx(i, t)] = __floats2half2_rn(u0, u1);
        }
        if (t < HDIM) {
            emb_s[t] = px * W_emb[t] + py * W_emb[HDIM + t] + b_emb[t];
            hv_s[t]  = g_h[i * HDIM + t];
        }
        __syncthreads();

        // Phase A: 6 GRU gate matvecs via float4 (thread = (gate g, c-quad q))
        if (t < 96) {
            int g = t >> 4, q = t & 15;
            int gg = (g < 3) ? g : g - 3;
            const float* Wt   = (g < 3) ? g_WihT : g_WhhT;
            const float* bias = (g < 3) ? b_ih : b_hh;
            const float* src  = (g < 3) ? emb_s : hv_s;
            float4 acc = *(const float4*)&bias[gg * 64 + q * 4];
            #pragma unroll 8
            for (int d = 0; d < HDIM; ++d) {
                float4 wv = *(const float4*)&Wt[d * G3 + gg * 64 + q * 4];
                float s = src[d];
                acc.x += s * wv.x; acc.y += s * wv.y;
                acc.z += s * wv.z; acc.w += s * wv.w;
            }
            *(float4*)&gate_s[g][q * 4] = acc;
        }
        __syncthreads();
        if (t < HDIM) {
            int c = t;
            float r = fsigmoid(gate_s[0][c] + gate_s[3][c]);
            float z = fsigmoid(gate_s[1][c] + gate_s[4][c]);
            float n = ftanh(gate_s[2][c] + r * gate_s[5][c]);
            float hn = (1.0f - z) * n + z * hv_s[c];
            g_h[i * HDIM + c] = hn;
            hn_s[c] = hn;
        }
        __syncthreads();

        // Phase B: hp = hn @ Wp2 + b_pool, float4 partials then reduce, f16 store
        if (t < 64) {
            int q = t & 15, dh = t >> 4;
            float4 acc = make_float4(0.0f, 0.0f, 0.0f, 0.0f);
            #pragma unroll
            for (int dd = 0; dd < 16; ++dd) {
                int d = dh * 16 + dd;
                float4 wv = *(const float4*)&W_pool[(HDIM + d) * HDIM + q * 4];
                float s = hn_s[d];
                acc.x += s * wv.x; acc.y += s * wv.y;
                acc.z += s * wv.z; acc.w += s * wv.w;
            }
            hpr_s[q][dh] = acc;
        }
        __syncthreads();
        if (t < 16) {
            int q = t;
            float4 a0 = hpr_s[q][0], a1 = hpr_s[q][1], a2 = hpr_s[q][2], a3 = hpr_s[q][3];
            float c0 = a0.x + a1.x + a2.x + a3.x + b_pool[q * 4 + 0];
            float c1 = a0.y + a1.y + a2.y + a3.y + b_pool[q * 4 + 1];
            float c2 = a0.z + a1.z + a2.z + a3.z + b_pool[q * 4 + 2];
            float c3 = a0.w + a1.w + a2.w + a3.w + b_pool[q * 4 + 3];
            g_hph[step + 1][pair_idx(i, 2 * q)]     = __floats2half2_rn(c0, c1);
            g_hph[step + 1][pair_idx(i, 2 * q + 1)] = __floats2half2_rn(c2, c3);
        }

        // ---- grid barrier (skip after last step) ----
        if (step == PRE - 1) break;
        __syncthreads();
        if (t == 0) {
            __threadfence();   // release: u/hp stores visible GPU-wide
            unsigned target = (unsigned)BATCH * (unsigned)(step + 1);
            unsigned old = atomicAdd(&g_bar_cnt, 1u);
            if (old + 1u == target) {
                atomicExch(&g_bar_rel, (unsigned)(step + 1));
            } else {
                unsigned v;
                do {
                    __nanosleep(128);
                    asm volatile("ld.global.cg.u32 %0, [%1];" : "=r"(v) : "l"(&g_bar_rel));
                } while (v < (unsigned)(step + 1));
            }
            __threadfence();
        }
        __syncthreads();
    }
}

// ---------------------------------------------------------------------------
extern "C" void kernel_launch(void* const* d_in, const int* in_sizes, int n_in,
                              void* d_out, int out_size)
{
    const float* hidden = (const float*)d_in[0];
    const float* gt     = (const float*)d_in[1];
    const float* W_emb  = (const float*)d_in[2];
    const float* b_emb  = (const float*)d_in[3];
    const float* W_ih   = (const float*)d_in[4];
    const float* W_hh   = (const float*)d_in[5];
    const float* b_ih   = (const float*)d_in[6];
    const float* b_hh   = (const float*)d_in[7];
    const float* W_pos  = (const float*)d_in[8];
    const float* b_pos  = (const float*)d_in[9];
    const float* W_rel  = (const float*)d_in[10];
    const float* b_rel  = (const float*)d_in[11];
    const float* W_pool = (const float*)d_in[12];
    const float* b_pool = (const float*)d_in[13];
    float* out = (float*)d_out;

    init_kernel<<<BATCH + G3 + 16, 64>>>(hidden, gt, W_ih, W_hh, W_rel, W_pool, b_pool, out);
    decode_kernel<<<BATCH, 128>>>(b_rel, W_emb, b_emb, b_ih, b_hh,
                                  W_pos, b_pos, W_rel, W_pool, b_pool, out);
}